// round 1
// baseline (speedup 1.0000x reference)
#include <cuda_runtime.h>
#include <cstdint>

#define NU 100000
#define NI 50000
#define EE 500000
#define C  128
#define LL 2
#define BB 1024

// ---------------- static device scratch (no runtime allocation) ----------------
__device__ float g_xu_a[NU * C];
__device__ float g_xu_b[NU * C];
__device__ float g_xi_a[NI * C];
__device__ float g_xi_b[NI * C];
__device__ float g_agg_u[NU * C];
__device__ float g_agg_i[NI * C];

// ---------------- helpers ----------------
__device__ __forceinline__ void ffma2(unsigned long long& d, unsigned long long a, unsigned long long b) {
    asm("fma.rn.f32x2 %0, %1, %2, %0;" : "+l"(d) : "l"(a), "l"(b));
}
__device__ __forceinline__ unsigned long long pack2(float lo, float hi) {
    unsigned long long r;
    asm("mov.b64 %0, {%1, %2};" : "=l"(r) : "f"(lo), "f"(hi));
    return r;
}
__device__ __forceinline__ float2 unpack2(unsigned long long v) {
    float2 r;
    asm("mov.b64 {%0, %1}, %2;" : "=f"(r.x), "=f"(r.y) : "l"(v));
    return r;
}

// ---------------- zero ----------------
__global__ void zero_kernel(float4* __restrict__ p, int n4) {
    int i = blockIdx.x * blockDim.x + threadIdx.x;
    int stride = gridDim.x * blockDim.x;
    float4 z = make_float4(0.f, 0.f, 0.f, 0.f);
    for (; i < n4; i += stride) p[i] = z;
}

// ---------------- edge scatter-add (segment_sum), warp per edge ----------------
__global__ void scatter_kernel(const float* __restrict__ x, const int* __restrict__ src,
                               const int* __restrict__ dst, float* __restrict__ agg, int E) {
    int gid = blockIdx.x * blockDim.x + threadIdx.x;
    int w = gid >> 5;
    int lane = gid & 31;
    if (w >= E) return;
    int s = __ldg(src + w);
    int d = __ldg(dst + w);
    float4 v = *reinterpret_cast<const float4*>(x + (size_t)s * C + lane * 4);
    float* a = agg + (size_t)d * C + lane * 4;
    asm volatile("red.global.add.v4.f32 [%0], {%1, %2, %3, %4};"
                 :: "l"(a), "f"(v.x), "f"(v.y), "f"(v.z), "f"(v.w) : "memory");
}

// ---------------- fused: out = relu(LN(agg@Wrel + x@Wroot + bias)) ----------------
#define TM   64
#define KT   32
#define PADK 33   // float2 slots per tile row
#define PADO 136  // floats per sOut row (keeps float4 reads aligned)

__global__ void __launch_bounds__(256, 1) gemm_ln_relu(
    const float* __restrict__ agg, const float* __restrict__ xin,
    const float* __restrict__ wrel, const float* __restrict__ wroot,
    const float* __restrict__ bias, const float* __restrict__ gln, const float* __restrict__ bln,
    float* __restrict__ out, int M)
{
    extern __shared__ float smem[];
    float* sWr   = smem;                   // 128*128
    float* sWo   = sWr + C * C;            // 128*128
    float* sA    = sWo + C * C;            // TM*PADK float2 (splatted)
    float* sX    = sA + TM * PADK * 2;
    float* sOut  = sX + TM * PADK * 2;     // TM*PADO
    float* sBias = sOut + TM * PADO;       // 128
    float* sG    = sBias + C;              // 128
    float* sB    = sG + C;                 // 128
    float* sMean = sB + C;                 // 64
    float* sRstd = sMean + TM;             // 64

    const int tid = threadIdx.x;
    const int tx = tid & 15;   // 16 col groups, 8 cols (4 f32x2) each
    const int ty = tid >> 4;   // 16 row groups, 4 rows each
    const int row0 = blockIdx.x * TM;

    // stage weights + LN params
    {
        const float4* gr_ = reinterpret_cast<const float4*>(wrel);
        const float4* go_ = reinterpret_cast<const float4*>(wroot);
        float4* swr = reinterpret_cast<float4*>(sWr);
        float4* swo = reinterpret_cast<float4*>(sWo);
        for (int i = tid; i < C * C / 4; i += 256) { swr[i] = gr_[i]; swo[i] = go_[i]; }
        if (tid < C) { sBias[tid] = bias[tid]; sG[tid] = gln[tid]; sB[tid] = bln[tid]; }
    }
    __syncthreads();

    unsigned long long acc[4][4];
#pragma unroll
    for (int j = 0; j < 4; ++j) {
        int c = 2 * (j * 16 + tx);
        unsigned long long b2 = pack2(sBias[c], sBias[c + 1]);
#pragma unroll
        for (int i = 0; i < 4; ++i) acc[i][j] = b2;
    }

    float2* sA2 = reinterpret_cast<float2*>(sA);
    float2* sX2 = reinterpret_cast<float2*>(sX);

    for (int t = 0; t < C / KT; ++t) {
        const int k0 = t * KT;
        // stage row tiles (splatted into float2 pairs)
#pragma unroll
        for (int p = 0; p < 2; ++p) {
            int idx = p * 256 + tid;      // 0..511
            int r = idx >> 3;
            int kq = (idx & 7) * 4;
            int grw = row0 + r;
            if (grw > M - 1) grw = M - 1;
            float4 va = *reinterpret_cast<const float4*>(agg + (size_t)grw * C + k0 + kq);
            float4 vx = *reinterpret_cast<const float4*>(xin + (size_t)grw * C + k0 + kq);
            float2* pa = sA2 + r * PADK + kq;
            float2* px = sX2 + r * PADK + kq;
            pa[0] = make_float2(va.x, va.x); pa[1] = make_float2(va.y, va.y);
            pa[2] = make_float2(va.z, va.z); pa[3] = make_float2(va.w, va.w);
            px[0] = make_float2(vx.x, vx.x); px[1] = make_float2(vx.y, vx.y);
            px[2] = make_float2(vx.z, vx.z); px[3] = make_float2(vx.w, vx.w);
        }
        __syncthreads();

        const unsigned long long* a_ = reinterpret_cast<const unsigned long long*>(sA);
        const unsigned long long* x_ = reinterpret_cast<const unsigned long long*>(sX);
        const unsigned long long* wrb = reinterpret_cast<const unsigned long long*>(sWr);
        const unsigned long long* wob = reinterpret_cast<const unsigned long long*>(sWo);
#pragma unroll
        for (int k = 0; k < KT; ++k) {
            unsigned long long wr[4], wo[4];
            const unsigned long long* wrp = wrb + (size_t)(k0 + k) * 64;
            const unsigned long long* wop = wob + (size_t)(k0 + k) * 64;
#pragma unroll
            for (int j = 0; j < 4; ++j) { wr[j] = wrp[j * 16 + tx]; wo[j] = wop[j * 16 + tx]; }
#pragma unroll
            for (int i = 0; i < 4; ++i) {
                unsigned long long av = a_[(ty * 4 + i) * PADK + k];
                unsigned long long xv = x_[(ty * 4 + i) * PADK + k];
#pragma unroll
                for (int j = 0; j < 4; ++j) {
                    ffma2(acc[i][j], av, wr[j]);
                    ffma2(acc[i][j], xv, wo[j]);
                }
            }
        }
        __syncthreads();
    }

    // ---- LayerNorm reduction ----
#pragma unroll
    for (int i = 0; i < 4; ++i) {
        int r = ty * 4 + i;
#pragma unroll
        for (int j = 0; j < 4; ++j) {
            int c = 2 * (j * 16 + tx);
            *reinterpret_cast<float2*>(sOut + r * PADO + c) = unpack2(acc[i][j]);
        }
    }
    __syncthreads();
    {
        int warp = tid >> 5, lane = tid & 31;
#pragma unroll
        for (int it = 0; it < TM / 8; ++it) {
            int r = warp * 8 + it;
            float4 v = *reinterpret_cast<const float4*>(sOut + r * PADO + lane * 4);
            float s = v.x + v.y + v.z + v.w;
            float ss = v.x * v.x + v.y * v.y + v.z * v.z + v.w * v.w;
#pragma unroll
            for (int o = 16; o > 0; o >>= 1) {
                s  += __shfl_xor_sync(0xffffffffu, s, o);
                ss += __shfl_xor_sync(0xffffffffu, ss, o);
            }
            if (lane == 0) {
                float mu = s * (1.f / 128.f);
                float var = ss * (1.f / 128.f) - mu * mu;
                sMean[r] = mu;
                sRstd[r] = rsqrtf(fmaxf(var, 0.f) + 1e-5f);
            }
        }
    }
    __syncthreads();

    // ---- normalize + affine + relu + store ----
#pragma unroll
    for (int i = 0; i < 4; ++i) {
        int r = ty * 4 + i;
        int gr = row0 + r;
        if (gr < M) {
            float mu = sMean[r], rs = sRstd[r];
#pragma unroll
            for (int j = 0; j < 4; ++j) {
                int c = 2 * (j * 16 + tx);
                float2 v = unpack2(acc[i][j]);
                float o0 = fmaxf(fmaf((v.x - mu) * rs, sG[c],     sB[c]),     0.f);
                float o1 = fmaxf(fmaf((v.y - mu) * rs, sG[c + 1], sB[c + 1]), 0.f);
                *reinterpret_cast<float2*>(out + (size_t)gr * C + c) = make_float2(o0, o1);
            }
        }
    }
}

// ---------------- head: out = xu[:B] @ lin_w + lin_b ----------------
__global__ void head_kernel(const float* __restrict__ xu, const float* __restrict__ w,
                            const float* __restrict__ b, float* __restrict__ out) {
    int gid = blockIdx.x * blockDim.x + threadIdx.x;
    int wd = gid >> 5, lane = gid & 31;
    if (wd >= BB) return;
    float4 v  = *reinterpret_cast<const float4*>(xu + (size_t)wd * C + lane * 4);
    float4 ww = *reinterpret_cast<const float4*>(w + lane * 4);
    float s = v.x * ww.x + v.y * ww.y + v.z * ww.z + v.w * ww.w;
#pragma unroll
    for (int o = 16; o > 0; o >>= 1) s += __shfl_xor_sync(0xffffffffu, s, o);
    if (lane == 0) out[wd] = s + b[0];
}

// ---------------- launch ----------------
extern "C" void kernel_launch(void* const* d_in, const int* in_sizes, int n_in,
                              void* d_out, int out_size) {
    const float* x_user  = (const float*)d_in[0];
    const float* x_item  = (const float*)d_in[1];
    const int* e_ui_src  = (const int*)d_in[2];
    const int* e_ui_dst  = (const int*)d_in[3];
    const int* e_iu_src  = (const int*)d_in[4];
    const int* e_iu_dst  = (const int*)d_in[5];
    const float* w_rel   = (const float*)d_in[6];   // [L,2,C,C]
    const float* w_root  = (const float*)d_in[7];   // [L,2,C,C]
    const float* bias    = (const float*)d_in[8];   // [L,2,C]
    const float* ln_g    = (const float*)d_in[9];   // [L,2,C]  (0=user,1=item)
    const float* ln_b    = (const float*)d_in[10];  // [L,2,C]
    const float* lin_w   = (const float*)d_in[11];  // [C,1]
    const float* lin_b   = (const float*)d_in[12];  // [1]
    float* out = (float*)d_out;

    float *xu_a, *xu_b, *xi_a, *xi_b, *aggu, *aggi;
    cudaGetSymbolAddress((void**)&xu_a, g_xu_a);
    cudaGetSymbolAddress((void**)&xu_b, g_xu_b);
    cudaGetSymbolAddress((void**)&xi_a, g_xi_a);
    cudaGetSymbolAddress((void**)&xi_b, g_xi_b);
    cudaGetSymbolAddress((void**)&aggu, g_agg_u);
    cudaGetSymbolAddress((void**)&aggi, g_agg_i);

    const int smem_bytes = (C * C * 2 + TM * PADK * 2 * 2 + TM * PADO + 3 * C + 2 * TM) * 4;
    cudaFuncSetAttribute(gemm_ln_relu, cudaFuncAttributeMaxDynamicSharedMemorySize, smem_bytes);

    const float* xu_in = x_user;
    const float* xi_in = x_item;
    float* xu_out = xu_a;
    float* xi_out = xi_a;

    const int scatter_blocks = (EE * 32 + 255) / 256;

    for (int l = 0; l < LL; ++l) {
        zero_kernel<<<2048, 256>>>((float4*)aggi, NI * C / 4);
        zero_kernel<<<2048, 256>>>((float4*)aggu, NU * C / 4);
        scatter_kernel<<<scatter_blocks, 256>>>(xu_in, e_ui_src, e_ui_dst, aggi, EE);
        scatter_kernel<<<scatter_blocks, 256>>>(xi_in, e_iu_src, e_iu_dst, aggu, EE);
        // items: out_i = agg_i@w_rel[l,0] + xi@w_root[l,0] + b[l,0]; LN uses ln_*[l,1]
        gemm_ln_relu<<<(NI + TM - 1) / TM, 256, smem_bytes>>>(
            aggi, xi_in,
            w_rel + (size_t)(l * 2 + 0) * C * C, w_root + (size_t)(l * 2 + 0) * C * C,
            bias + (l * 2 + 0) * C, ln_g + (l * 2 + 1) * C, ln_b + (l * 2 + 1) * C,
            xi_out, NI);
        // users: out_u = agg_u@w_rel[l,1] + xu@w_root[l,1] + b[l,1]; LN uses ln_*[l,0]
        gemm_ln_relu<<<(NU + TM - 1) / TM, 256, smem_bytes>>>(
            aggu, xu_in,
            w_rel + (size_t)(l * 2 + 1) * C * C, w_root + (size_t)(l * 2 + 1) * C * C,
            bias + (l * 2 + 1) * C, ln_g + (l * 2 + 0) * C, ln_b + (l * 2 + 0) * C,
            xu_out, NU);
        xu_in = xu_out; xi_in = xi_out;
        xu_out = xu_b;  xi_out = xi_b;
    }
    head_kernel<<<(BB * 32 + 255) / 256, 256>>>(xu_in, lin_w, lin_b, out);
}

// round 3
// speedup vs baseline: 1.1806x; 1.1806x over previous
#include <cuda_runtime.h>
#include <cstdint>

#define NU 100000
#define NI 50000
#define EE 500000
#define C  128
#define LL 2
#define BB 1024

// ---------------- static device scratch ----------------
__device__ float g_xu_a[NU * C];
__device__ float g_xu_b[NU * C];
__device__ float g_xi_a[NI * C];
__device__ float g_xi_b[NI * C];
__device__ float g_agg_u[NU * C];
__device__ float g_agg_i[NI * C];
// fragment-ordered split weights: [lt(4)][k8(32)][ntile(16)][lane(32)] x float4
__device__ __align__(16) float g_wfrag[4 * 32 * 16 * 32 * 4];

// ---------------- helpers ----------------
__device__ __forceinline__ float tf32_rna(float x) {
    uint32_t u;
    asm("cvt.rna.tf32.f32 %0, %1;" : "=r"(u) : "f"(x));
    return __uint_as_float(u);
}
__device__ __forceinline__ void mma8(float* c, uint32_t a0, uint32_t a1, uint32_t a2, uint32_t a3,
                                     uint32_t b0, uint32_t b1) {
    asm("mma.sync.aligned.m16n8k8.row.col.f32.tf32.tf32.f32 "
        "{%0,%1,%2,%3},{%4,%5,%6,%7},{%8,%9},{%0,%1,%2,%3};"
        : "+f"(c[0]), "+f"(c[1]), "+f"(c[2]), "+f"(c[3])
        : "r"(a0), "r"(a1), "r"(a2), "r"(a3), "r"(b0), "r"(b1));
}

// ---------------- zero ----------------
__global__ void zero_kernel(float4* __restrict__ p, int n4) {
    int i = blockIdx.x * blockDim.x + threadIdx.x;
    int stride = gridDim.x * blockDim.x;
    float4 z = make_float4(0.f, 0.f, 0.f, 0.f);
    for (; i < n4; i += stride) p[i] = z;
}

// ---------------- edge scatter-add ----------------
__global__ void scatter_kernel(const float* __restrict__ x, const int* __restrict__ src,
                               const int* __restrict__ dst, float* __restrict__ agg, int E) {
    int gid = blockIdx.x * blockDim.x + threadIdx.x;
    int w = gid >> 5;
    int lane = gid & 31;
    if (w >= E) return;
    int s = __ldg(src + w);
    int d = __ldg(dst + w);
    float4 v = *reinterpret_cast<const float4*>(x + (size_t)s * C + lane * 4);
    float* a = agg + (size_t)d * C + lane * 4;
    asm volatile("red.global.add.v4.f32 [%0], {%1, %2, %3, %4};"
                 :: "l"(a), "f"(v.x), "f"(v.y), "f"(v.z), "f"(v.w) : "memory");
}

// ---------------- weight prep: tf32 hi/lo split into per-lane fragment order ----------------
// out[gid] (float4) = (b0h, b1h, b0l, b1l) for mma.m16n8k8 B fragment (col-major):
//   b0: k = k8*8 + (lane&3), n = ntile*8 + (lane>>2);  b1: k+4, same n
__global__ void prep_w(const float* __restrict__ wrel, const float* __restrict__ wroot,
                       float4* __restrict__ outw) {
    int gid = blockIdx.x * blockDim.x + threadIdx.x;   // [lt][k8][ntile][lane]
    if (gid >= 4 * 32 * 16 * 32) return;
    int lane = gid & 31;
    int nt   = (gid >> 5) & 15;
    int k8   = (gid >> 9) & 31;
    int lt   = gid >> 14;
    int n  = nt * 8 + (lane >> 2);
    int k0 = k8 * 8 + (lane & 3);
    int k1 = k0 + 4;
    float w0 = (k0 < 128) ? wrel[((size_t)lt * 128 + k0) * 128 + n]
                          : wroot[((size_t)lt * 128 + (k0 - 128)) * 128 + n];
    float w1 = (k1 < 128) ? wrel[((size_t)lt * 128 + k1) * 128 + n]
                          : wroot[((size_t)lt * 128 + (k1 - 128)) * 128 + n];
    float h0 = tf32_rna(w0), l0 = tf32_rna(w0 - h0);
    float h1 = tf32_rna(w1), l1 = tf32_rna(w1 - h1);
    outw[gid] = make_float4(h0, h1, l0, l1);
}

// ---------------- fused tf32 mma.sync GEMM + bias + LN + ReLU ----------------
// D[256,128] = [agg|x][256,256] @ Wcat[256,128] via 3-chain tf32 split.
// 512 threads = 16 warps (8 m-groups x 2 n-groups), warp tile 32x64.
// smem: A stage [256 rows x 36 floats (16 k-pairs hi/lo, pad)] = 9216 floats,
//       overlaid by sOut [256 x 132] = 33792 floats; params at 33792..34175.
#define A_STRIDE 36
#define O_STRIDE 132
#define SM_PAR   (256 * O_STRIDE)
#define GEMM_SMEM_BYTES ((SM_PAR + 384) * 4)

__global__ void __launch_bounds__(512, 1) gemm_tc(
    const float* __restrict__ agg, const float* __restrict__ xin,
    const float4* __restrict__ wfrag,
    const float* __restrict__ bias, const float* __restrict__ gln, const float* __restrict__ blnv,
    float* __restrict__ out, int M)
{
    extern __shared__ float smem[];
    const int tid  = threadIdx.x;
    const int lane = tid & 31;
    const int wid  = tid >> 5;        // 0..15
    const int wm   = wid >> 1;        // 0..7
    const int wn   = wid & 1;         // 0..1
    const int row0 = blockIdx.x * 256;

    if (tid < 128) {
        smem[SM_PAR + tid]       = bias[tid];
        smem[SM_PAR + 128 + tid] = gln[tid];
        smem[SM_PAR + 256 + tid] = blnv[tid];
    }
    __syncthreads();

    // accumulators init to bias (columns only depend on (wn, nt, lane&3))
    float c[2][8][4];
#pragma unroll
    for (int nt = 0; nt < 8; ++nt) {
        int col = wn * 64 + nt * 8 + 2 * (lane & 3);
        float b0 = smem[SM_PAR + col], b1 = smem[SM_PAR + col + 1];
#pragma unroll
        for (int mt = 0; mt < 2; ++mt) {
            c[mt][nt][0] = b0; c[mt][nt][1] = b1;
            c[mt][nt][2] = b0; c[mt][nt][3] = b1;
        }
    }

    for (int s = 0; s < 16; ++s) {
        const float* src = (s < 8) ? agg : xin;
        const int kg = (s & 7) * 16;
        __syncthreads();
        // stage A: 256 rows x 16 k, split hi/lo interleaved
#pragma unroll
        for (int h = 0; h < 2; ++h) {
            int idx = h * 512 + tid;
            int r = idx >> 2;
            int kq = (idx & 3) * 4;
            int gr = row0 + r; if (gr > M - 1) gr = M - 1;
            float4 v = *reinterpret_cast<const float4*>(src + (size_t)gr * C + kg + kq);
            float h0 = tf32_rna(v.x), l0 = tf32_rna(v.x - h0);
            float h1 = tf32_rna(v.y), l1 = tf32_rna(v.y - h1);
            float h2 = tf32_rna(v.z), l2 = tf32_rna(v.z - h2);
            float h3 = tf32_rna(v.w), l3 = tf32_rna(v.w - h3);
            float* p = smem + r * A_STRIDE + kq * 2;
            *reinterpret_cast<float4*>(p)     = make_float4(h0, l0, h1, l1);
            *reinterpret_cast<float4*>(p + 4) = make_float4(h2, l2, h3, l3);
        }
        __syncthreads();

#pragma unroll
        for (int kk = 0; kk < 2; ++kk) {
            const int k8g = s * 2 + kk;
            // A fragments (hi in .x, lo in .y)
            uint2 af[2][4];
#pragma unroll
            for (int mt = 0; mt < 2; ++mt) {
                int rbase = wm * 32 + mt * 16 + (lane >> 2);
                const float* pa = smem + rbase * A_STRIDE + (kk * 8 + (lane & 3)) * 2;
                af[mt][0] = *reinterpret_cast<const uint2*>(pa);
                af[mt][1] = *reinterpret_cast<const uint2*>(pa + 8 * A_STRIDE);
                af[mt][2] = *reinterpret_cast<const uint2*>(pa + 8);
                af[mt][3] = *reinterpret_cast<const uint2*>(pa + 8 * A_STRIDE + 8);
            }
            const float4* wp = wfrag + ((size_t)k8g * 16 + wn * 8) * 32 + lane;
#pragma unroll
            for (int nt = 0; nt < 8; ++nt) {
                uint4 bf = *reinterpret_cast<const uint4*>(wp + nt * 32);
#pragma unroll
                for (int mt = 0; mt < 2; ++mt) {
                    mma8(c[mt][nt], af[mt][0].x, af[mt][1].x, af[mt][2].x, af[mt][3].x, bf.x, bf.y); // hi*hi
                    mma8(c[mt][nt], af[mt][0].y, af[mt][1].y, af[mt][2].y, af[mt][3].y, bf.x, bf.y); // lo*hi
                    mma8(c[mt][nt], af[mt][0].x, af[mt][1].x, af[mt][2].x, af[mt][3].x, bf.z, bf.w); // hi*lo
                }
            }
        }
    }

    __syncthreads();   // all A reads done; reuse smem as sOut
    // stage C to smem
#pragma unroll
    for (int mt = 0; mt < 2; ++mt) {
        int r = wm * 32 + mt * 16 + (lane >> 2);
#pragma unroll
        for (int nt = 0; nt < 8; ++nt) {
            int col = wn * 64 + nt * 8 + 2 * (lane & 3);
            *reinterpret_cast<float2*>(smem + (size_t)r * O_STRIDE + col)       = make_float2(c[mt][nt][0], c[mt][nt][1]);
            *reinterpret_cast<float2*>(smem + (size_t)(r + 8) * O_STRIDE + col) = make_float2(c[mt][nt][2], c[mt][nt][3]);
        }
    }
    __syncthreads();

    // LN + ReLU + store: warp per row
#pragma unroll 4
    for (int it = 0; it < 16; ++it) {
        int r = wid * 16 + it;
        float4 v = *reinterpret_cast<const float4*>(smem + (size_t)r * O_STRIDE + lane * 4);
        float sum = v.x + v.y + v.z + v.w;
        float ss  = v.x * v.x + v.y * v.y + v.z * v.z + v.w * v.w;
#pragma unroll
        for (int o = 16; o > 0; o >>= 1) {
            sum += __shfl_xor_sync(0xffffffffu, sum, o);
            ss  += __shfl_xor_sync(0xffffffffu, ss, o);
        }
        float mu = sum * (1.f / 128.f);
        float rstd = rsqrtf(fmaxf(ss * (1.f / 128.f) - mu * mu, 0.f) + 1e-5f);
        int gr = row0 + r;
        if (gr < M) {
            int cb = lane * 4;
            float o0 = fmaxf(fmaf((v.x - mu) * rstd, smem[SM_PAR + 128 + cb],     smem[SM_PAR + 256 + cb]),     0.f);
            float o1 = fmaxf(fmaf((v.y - mu) * rstd, smem[SM_PAR + 128 + cb + 1], smem[SM_PAR + 256 + cb + 1]), 0.f);
            float o2 = fmaxf(fmaf((v.z - mu) * rstd, smem[SM_PAR + 128 + cb + 2], smem[SM_PAR + 256 + cb + 2]), 0.f);
            float o3 = fmaxf(fmaf((v.w - mu) * rstd, smem[SM_PAR + 128 + cb + 3], smem[SM_PAR + 256 + cb + 3]), 0.f);
            *reinterpret_cast<float4*>(out + (size_t)gr * C + cb) = make_float4(o0, o1, o2, o3);
        }
    }
}

// ---------------- head ----------------
__global__ void head_kernel(const float* __restrict__ xu, const float* __restrict__ w,
                            const float* __restrict__ b, float* __restrict__ out) {
    int gid = blockIdx.x * blockDim.x + threadIdx.x;
    int wd = gid >> 5, lane = gid & 31;
    if (wd >= BB) return;
    float4 v  = *reinterpret_cast<const float4*>(xu + (size_t)wd * C + lane * 4);
    float4 ww = *reinterpret_cast<const float4*>(w + lane * 4);
    float s = v.x * ww.x + v.y * ww.y + v.z * ww.z + v.w * ww.w;
#pragma unroll
    for (int o = 16; o > 0; o >>= 1) s += __shfl_xor_sync(0xffffffffu, s, o);
    if (lane == 0) out[wd] = s + b[0];
}

// ---------------- launch ----------------
extern "C" void kernel_launch(void* const* d_in, const int* in_sizes, int n_in,
                              void* d_out, int out_size) {
    const float* x_user  = (const float*)d_in[0];
    const float* x_item  = (const float*)d_in[1];
    const int* e_ui_src  = (const int*)d_in[2];
    const int* e_ui_dst  = (const int*)d_in[3];
    const int* e_iu_src  = (const int*)d_in[4];
    const int* e_iu_dst  = (const int*)d_in[5];
    const float* w_rel   = (const float*)d_in[6];   // [L,2,C,C]
    const float* w_root  = (const float*)d_in[7];
    const float* bias    = (const float*)d_in[8];   // [L,2,C]
    const float* ln_g    = (const float*)d_in[9];
    const float* ln_b    = (const float*)d_in[10];
    const float* lin_w   = (const float*)d_in[11];
    const float* lin_b   = (const float*)d_in[12];
    float* out = (float*)d_out;

    float *xu_a, *xu_b, *xi_a, *xi_b, *aggu, *aggi;
    float4* wfrag;
    cudaGetSymbolAddress((void**)&xu_a, g_xu_a);
    cudaGetSymbolAddress((void**)&xu_b, g_xu_b);
    cudaGetSymbolAddress((void**)&xi_a, g_xi_a);
    cudaGetSymbolAddress((void**)&xi_b, g_xi_b);
    cudaGetSymbolAddress((void**)&aggu, g_agg_u);
    cudaGetSymbolAddress((void**)&aggi, g_agg_i);
    cudaGetSymbolAddress((void**)&wfrag, g_wfrag);

    cudaFuncSetAttribute(gemm_tc, cudaFuncAttributeMaxDynamicSharedMemorySize, GEMM_SMEM_BYTES);

    prep_w<<<(4 * 32 * 16 * 32 + 255) / 256, 256>>>(w_rel, w_root, wfrag);

    const float* xu_in = x_user;
    const float* xi_in = x_item;
    float* xu_out = xu_a;
    float* xi_out = xi_a;

    const int scatter_blocks = (EE * 32 + 255) / 256;

    for (int l = 0; l < LL; ++l) {
        zero_kernel<<<2048, 256>>>((float4*)aggi, NI * C / 4);
        zero_kernel<<<2048, 256>>>((float4*)aggu, NU * C / 4);
        scatter_kernel<<<scatter_blocks, 256>>>(xu_in, e_ui_src, e_ui_dst, aggi, EE);
        scatter_kernel<<<scatter_blocks, 256>>>(xi_in, e_iu_src, e_iu_dst, aggu, EE);
        // items: weights (l,0); LN params (l,1)
        gemm_tc<<<(NI + 255) / 256, 512, GEMM_SMEM_BYTES>>>(
            aggi, xi_in, wfrag + (size_t)(l * 2 + 0) * 32 * 16 * 32,
            bias + (l * 2 + 0) * C, ln_g + (l * 2 + 1) * C, ln_b + (l * 2 + 1) * C,
            xi_out, NI);
        // users: weights (l,1); LN params (l,0)
        gemm_tc<<<(NU + 255) / 256, 512, GEMM_SMEM_BYTES>>>(
            aggu, xu_in, wfrag + (size_t)(l * 2 + 1) * 32 * 16 * 32,
            bias + (l * 2 + 1) * C, ln_g + (l * 2 + 0) * C, ln_b + (l * 2 + 0) * C,
            xu_out, NU);
        xu_in = xu_out; xi_in = xi_out;
        xu_out = xu_b;  xi_out = xi_b;
    }
    head_kernel<<<(BB * 32 + 255) / 256, 256>>>(xu_in, lin_w, lin_b, out);
}

// round 4
// speedup vs baseline: 1.7862x; 1.5129x over previous
#include <cuda_runtime.h>
#include <cuda_fp16.h>
#include <cstdint>

#define NU 100000
#define NI 50000
#define EE 500000
#define C  128
#define LL 2
#define BB 1024

// ---------------- static device scratch ----------------
__device__ float g_xu_a[NU * C];
__device__ float g_xu_b[NU * C];
__device__ float g_xi_a[NI * C];
__device__ float g_xi_b[NI * C];
__device__ float g_agg_u[NU * C];
__device__ float g_agg_i[NI * C];
// fragment-ordered fp16 split weights: [lt(4)][k16(16)][ntile(16)][lane(32)] uint4=(bh0,bh1,bl0,bl1)
__device__ __align__(16) uint4 g_wfrag[4 * 16 * 16 * 32];

// ---------------- helpers ----------------
__device__ __forceinline__ uint32_t h2u(half2 h) { return *reinterpret_cast<uint32_t*>(&h); }
__device__ __forceinline__ void split16(float x, half& h, half& l) {
    h = __float2half_rn(x);
    l = __float2half_rn(x - __half2float(h));
}
__device__ __forceinline__ void mma16(float* c, uint32_t a0, uint32_t a1, uint32_t a2, uint32_t a3,
                                      uint32_t b0, uint32_t b1) {
    asm("mma.sync.aligned.m16n8k16.row.col.f32.f16.f16.f32 "
        "{%0,%1,%2,%3},{%4,%5,%6,%7},{%8,%9},{%0,%1,%2,%3};"
        : "+f"(c[0]), "+f"(c[1]), "+f"(c[2]), "+f"(c[3])
        : "r"(a0), "r"(a1), "r"(a2), "r"(a3), "r"(b0), "r"(b1));
}

// ---------------- zero ----------------
__global__ void zero_kernel(float4* __restrict__ p, int n4) {
    int i = blockIdx.x * blockDim.x + threadIdx.x;
    int stride = gridDim.x * blockDim.x;
    float4 z = make_float4(0.f, 0.f, 0.f, 0.f);
    for (; i < n4; i += stride) p[i] = z;
}

// ---------------- edge scatter-add: 4 edges per warp (MLP=4) ----------------
__global__ void scatter_kernel(const float* __restrict__ x, const int* __restrict__ src,
                               const int* __restrict__ dst, float* __restrict__ agg, int E) {
    int gid = blockIdx.x * blockDim.x + threadIdx.x;
    int w = gid >> 5;
    int lane = gid & 31;
    int e0 = w * 4;
    if (e0 >= E) return;
    int4 s4 = *reinterpret_cast<const int4*>(src + e0);   // broadcast
    int4 d4 = *reinterpret_cast<const int4*>(dst + e0);
    float4 v0 = __ldg(reinterpret_cast<const float4*>(x + (size_t)s4.x * C) + lane);
    float4 v1 = __ldg(reinterpret_cast<const float4*>(x + (size_t)s4.y * C) + lane);
    float4 v2 = __ldg(reinterpret_cast<const float4*>(x + (size_t)s4.z * C) + lane);
    float4 v3 = __ldg(reinterpret_cast<const float4*>(x + (size_t)s4.w * C) + lane);
    float* a0 = agg + (size_t)d4.x * C + lane * 4;
    float* a1 = agg + (size_t)d4.y * C + lane * 4;
    float* a2 = agg + (size_t)d4.z * C + lane * 4;
    float* a3 = agg + (size_t)d4.w * C + lane * 4;
    asm volatile("red.global.add.v4.f32 [%0], {%1, %2, %3, %4};" :: "l"(a0), "f"(v0.x), "f"(v0.y), "f"(v0.z), "f"(v0.w) : "memory");
    asm volatile("red.global.add.v4.f32 [%0], {%1, %2, %3, %4};" :: "l"(a1), "f"(v1.x), "f"(v1.y), "f"(v1.z), "f"(v1.w) : "memory");
    asm volatile("red.global.add.v4.f32 [%0], {%1, %2, %3, %4};" :: "l"(a2), "f"(v2.x), "f"(v2.y), "f"(v2.z), "f"(v2.w) : "memory");
    asm volatile("red.global.add.v4.f32 [%0], {%1, %2, %3, %4};" :: "l"(a3), "f"(v3.x), "f"(v3.y), "f"(v3.z), "f"(v3.w) : "memory");
}

// ---------------- weight prep: fp16 hi/lo split into per-lane fragment order ----------------
// B frag m16n8k16 col-major: b0 = (k0, k0+1), b1 = (k0+8, k0+9), n = nt*8 + lane>>2, k0 = k16*16 + (lane&3)*2
__global__ void prep_w(const float* __restrict__ wrel, const float* __restrict__ wroot,
                       uint4* __restrict__ outw) {
    int gid = blockIdx.x * blockDim.x + threadIdx.x;   // [lt][k16][nt][lane]
    if (gid >= 4 * 16 * 16 * 32) return;
    int lane = gid & 31;
    int nt   = (gid >> 5) & 15;
    int k16  = (gid >> 9) & 15;
    int lt   = gid >> 13;
    int n  = nt * 8 + (lane >> 2);
    int k0 = k16 * 16 + (lane & 3) * 2;
    float w[4];
#pragma unroll
    for (int j = 0; j < 4; ++j) {
        int k = k0 + (j >> 1) * 8 + (j & 1);
        w[j] = (k < 128) ? wrel[((size_t)lt * 128 + k) * 128 + n]
                         : wroot[((size_t)lt * 128 + (k - 128)) * 128 + n];
    }
    half h[4], l[4];
#pragma unroll
    for (int j = 0; j < 4; ++j) split16(w[j], h[j], l[j]);
    outw[gid] = make_uint4(h2u(__halves2half2(h[0], h[1])), h2u(__halves2half2(h[2], h[3])),
                           h2u(__halves2half2(l[0], l[1])), h2u(__halves2half2(l[2], l[3])));
}

// ---------------- fused fp16 mma.sync GEMM + bias + LN + ReLU ----------------
// D[256,128] = [agg|x][256,256] @ Wcat[256,128], 3-chain fp16 split, 16 k16-stages.
// A stage (per buf): 256 rows x 24 words; word[2p]=hi2(k2p,k2p+1), word[2p+1]=lo2. Stride 24 (conflict-free LDS.64).
// sOut overlays smem; params at word SM_PAR.
#define A_STRIDE 24
#define A_BUF_W  (256 * A_STRIDE)
#define O_STRIDE 132
#define SM_PAR   (256 * O_STRIDE)
#define GEMM_SMEM_BYTES ((SM_PAR + 384) * 4)

__global__ void __launch_bounds__(512, 1) gemm_tc(
    const float* __restrict__ agg, const float* __restrict__ xin,
    const uint4* __restrict__ wfrag,
    const float* __restrict__ bias, const float* __restrict__ gln, const float* __restrict__ blnv,
    float* __restrict__ out, int M)
{
    extern __shared__ float smem[];
    uint32_t* aw = reinterpret_cast<uint32_t*>(smem);
    const int tid  = threadIdx.x;
    const int lane = tid & 31;
    const int wid  = tid >> 5;        // 0..15
    const int wm   = wid >> 1;        // 0..7
    const int wn   = wid & 1;         // 0..1
    const int row0 = blockIdx.x * 256;

    if (tid < 128) {
        smem[SM_PAR + tid]       = bias[tid];
        smem[SM_PAR + 128 + tid] = gln[tid];
        smem[SM_PAR + 256 + tid] = blnv[tid];
    }

    // per-thread staging coords
    const int sr0 = tid >> 2, sq0 = (tid & 3);            // h=0
    const int sr1 = (512 + tid) >> 2, sq1 = (tid & 3);    // h=1
    int gr0 = row0 + sr0; if (gr0 > M - 1) gr0 = M - 1;
    int gr1 = row0 + sr1; if (gr1 > M - 1) gr1 = M - 1;

    float c[2][8][4];

    // prologue: load stage 0 (agg, kg=0)
    float4 pre0 = __ldg(reinterpret_cast<const float4*>(agg + (size_t)gr0 * C) + sq0);
    float4 pre1 = __ldg(reinterpret_cast<const float4*>(agg + (size_t)gr1 * C) + sq1);

    __syncthreads();   // params visible

    // init accumulators to bias
#pragma unroll
    for (int nt = 0; nt < 8; ++nt) {
        int col = wn * 64 + nt * 8 + 2 * (lane & 3);
        float b0 = smem[SM_PAR + col], b1 = smem[SM_PAR + col + 1];
#pragma unroll
        for (int mt = 0; mt < 2; ++mt) {
            c[mt][nt][0] = b0; c[mt][nt][1] = b1;
            c[mt][nt][2] = b0; c[mt][nt][3] = b1;
        }
    }

    // store stage 0
    {
        half h0, l0, h1, l1, h2, l2, h3, l3;
        split16(pre0.x, h0, l0); split16(pre0.y, h1, l1); split16(pre0.z, h2, l2); split16(pre0.w, h3, l3);
        *reinterpret_cast<uint4*>(aw + sr0 * A_STRIDE + sq0 * 4) =
            make_uint4(h2u(__halves2half2(h0, h1)), h2u(__halves2half2(l0, l1)),
                       h2u(__halves2half2(h2, h3)), h2u(__halves2half2(l2, l3)));
        split16(pre1.x, h0, l0); split16(pre1.y, h1, l1); split16(pre1.z, h2, l2); split16(pre1.w, h3, l3);
        *reinterpret_cast<uint4*>(aw + sr1 * A_STRIDE + sq1 * 4) =
            make_uint4(h2u(__halves2half2(h0, h1)), h2u(__halves2half2(l0, l1)),
                       h2u(__halves2half2(h2, h3)), h2u(__halves2half2(l2, l3)));
    }
    __syncthreads();

    for (int s = 0; s < 16; ++s) {
        const int buf = s & 1;
        // prefetch stage s+1
        if (s < 15) {
            const float* src = (s + 1 < 8) ? agg : xin;
            const int kg = ((s + 1) & 7) * 16;
            pre0 = __ldg(reinterpret_cast<const float4*>(src + (size_t)gr0 * C + kg) + sq0);
            pre1 = __ldg(reinterpret_cast<const float4*>(src + (size_t)gr1 * C + kg) + sq1);
        }

        // MMAs on buf
        const uint32_t* ab = aw + buf * A_BUF_W;
        uint2 u[2][4];
#pragma unroll
        for (int mt = 0; mt < 2; ++mt) {
            const uint32_t* pa = ab + (wm * 32 + mt * 16 + (lane >> 2)) * A_STRIDE + 2 * (lane & 3);
            u[mt][0] = *reinterpret_cast<const uint2*>(pa);
            u[mt][1] = *reinterpret_cast<const uint2*>(pa + 8 * A_STRIDE);
            u[mt][2] = *reinterpret_cast<const uint2*>(pa + 8);
            u[mt][3] = *reinterpret_cast<const uint2*>(pa + 8 * A_STRIDE + 8);
        }
        const uint4* wp = wfrag + ((size_t)s * 16 + wn * 8) * 32 + lane;
#pragma unroll
        for (int nt = 0; nt < 8; ++nt) {
            uint4 bf = __ldg(wp + nt * 32);
#pragma unroll
            for (int mt = 0; mt < 2; ++mt) {
                mma16(c[mt][nt], u[mt][0].x, u[mt][1].x, u[mt][2].x, u[mt][3].x, bf.x, bf.y); // hi*hi
                mma16(c[mt][nt], u[mt][0].y, u[mt][1].y, u[mt][2].y, u[mt][3].y, bf.x, bf.y); // lo*hi
                mma16(c[mt][nt], u[mt][0].x, u[mt][1].x, u[mt][2].x, u[mt][3].x, bf.z, bf.w); // hi*lo
            }
        }

        // store stage s+1 into other buffer
        if (s < 15) {
            uint32_t* dbw = aw + (buf ^ 1) * A_BUF_W;
            half h0, l0, h1, l1, h2, l2, h3, l3;
            split16(pre0.x, h0, l0); split16(pre0.y, h1, l1); split16(pre0.z, h2, l2); split16(pre0.w, h3, l3);
            *reinterpret_cast<uint4*>(dbw + sr0 * A_STRIDE + sq0 * 4) =
                make_uint4(h2u(__halves2half2(h0, h1)), h2u(__halves2half2(l0, l1)),
                           h2u(__halves2half2(h2, h3)), h2u(__halves2half2(l2, l3)));
            split16(pre1.x, h0, l0); split16(pre1.y, h1, l1); split16(pre1.z, h2, l2); split16(pre1.w, h3, l3);
            *reinterpret_cast<uint4*>(dbw + sr1 * A_STRIDE + sq1 * 4) =
                make_uint4(h2u(__halves2half2(h0, h1)), h2u(__halves2half2(l0, l1)),
                           h2u(__halves2half2(h2, h3)), h2u(__halves2half2(l2, l3)));
        }
        __syncthreads();
    }

    // ---- stage C to smem (overlays A buffers) ----
#pragma unroll
    for (int mt = 0; mt < 2; ++mt) {
        int r = wm * 32 + mt * 16 + (lane >> 2);
#pragma unroll
        for (int nt = 0; nt < 8; ++nt) {
            int col = wn * 64 + nt * 8 + 2 * (lane & 3);
            *reinterpret_cast<float2*>(smem + (size_t)r * O_STRIDE + col)       = make_float2(c[mt][nt][0], c[mt][nt][1]);
            *reinterpret_cast<float2*>(smem + (size_t)(r + 8) * O_STRIDE + col) = make_float2(c[mt][nt][2], c[mt][nt][3]);
        }
    }
    __syncthreads();

    // ---- LN + ReLU + coalesced store: warp per row ----
#pragma unroll 4
    for (int it = 0; it < 16; ++it) {
        int r = wid * 16 + it;
        float4 v = *reinterpret_cast<const float4*>(smem + (size_t)r * O_STRIDE + lane * 4);
        float sum = v.x + v.y + v.z + v.w;
        float ss  = v.x * v.x + v.y * v.y + v.z * v.z + v.w * v.w;
#pragma unroll
        for (int o = 16; o > 0; o >>= 1) {
            sum += __shfl_xor_sync(0xffffffffu, sum, o);
            ss  += __shfl_xor_sync(0xffffffffu, ss, o);
        }
        float mu = sum * (1.f / 128.f);
        float rstd = rsqrtf(fmaxf(ss * (1.f / 128.f) - mu * mu, 0.f) + 1e-5f);
        int gr = row0 + r;
        if (gr < M) {
            int cb = lane * 4;
            float o0 = fmaxf(fmaf((v.x - mu) * rstd, smem[SM_PAR + 128 + cb],     smem[SM_PAR + 256 + cb]),     0.f);
            float o1 = fmaxf(fmaf((v.y - mu) * rstd, smem[SM_PAR + 128 + cb + 1], smem[SM_PAR + 256 + cb + 1]), 0.f);
            float o2 = fmaxf(fmaf((v.z - mu) * rstd, smem[SM_PAR + 128 + cb + 2], smem[SM_PAR + 256 + cb + 2]), 0.f);
            float o3 = fmaxf(fmaf((v.w - mu) * rstd, smem[SM_PAR + 128 + cb + 3], smem[SM_PAR + 256 + cb + 3]), 0.f);
            *reinterpret_cast<float4*>(out + (size_t)gr * C + cb) = make_float4(o0, o1, o2, o3);
        }
    }
}

// ---------------- head ----------------
__global__ void head_kernel(const float* __restrict__ xu, const float* __restrict__ w,
                            const float* __restrict__ b, float* __restrict__ out) {
    int gid = blockIdx.x * blockDim.x + threadIdx.x;
    int wd = gid >> 5, lane = gid & 31;
    if (wd >= BB) return;
    float4 v  = *reinterpret_cast<const float4*>(xu + (size_t)wd * C + lane * 4);
    float4 ww = *reinterpret_cast<const float4*>(w + lane * 4);
    float s = v.x * ww.x + v.y * ww.y + v.z * ww.z + v.w * ww.w;
#pragma unroll
    for (int o = 16; o > 0; o >>= 1) s += __shfl_xor_sync(0xffffffffu, s, o);
    if (lane == 0) out[wd] = s + b[0];
}

// ---------------- launch ----------------
extern "C" void kernel_launch(void* const* d_in, const int* in_sizes, int n_in,
                              void* d_out, int out_size) {
    const float* x_user  = (const float*)d_in[0];
    const float* x_item  = (const float*)d_in[1];
    const int* e_ui_src  = (const int*)d_in[2];
    const int* e_ui_dst  = (const int*)d_in[3];
    const int* e_iu_src  = (const int*)d_in[4];
    const int* e_iu_dst  = (const int*)d_in[5];
    const float* w_rel   = (const float*)d_in[6];   // [L,2,C,C]
    const float* w_root  = (const float*)d_in[7];
    const float* bias    = (const float*)d_in[8];   // [L,2,C]
    const float* ln_g    = (const float*)d_in[9];
    const float* ln_b    = (const float*)d_in[10];
    const float* lin_w   = (const float*)d_in[11];
    const float* lin_b   = (const float*)d_in[12];
    float* out = (float*)d_out;

    float *xu_a, *xu_b, *xi_a, *xi_b, *aggu, *aggi;
    uint4* wfrag;
    cudaGetSymbolAddress((void**)&xu_a, g_xu_a);
    cudaGetSymbolAddress((void**)&xu_b, g_xu_b);
    cudaGetSymbolAddress((void**)&xi_a, g_xi_a);
    cudaGetSymbolAddress((void**)&xi_b, g_xi_b);
    cudaGetSymbolAddress((void**)&aggu, g_agg_u);
    cudaGetSymbolAddress((void**)&aggi, g_agg_i);
    cudaGetSymbolAddress((void**)&wfrag, g_wfrag);

    cudaFuncSetAttribute(gemm_tc, cudaFuncAttributeMaxDynamicSharedMemorySize, GEMM_SMEM_BYTES);

    prep_w<<<(4 * 16 * 16 * 32 + 255) / 256, 256>>>(w_rel, w_root, wfrag);

    const float* xu_in = x_user;
    const float* xi_in = x_item;
    float* xu_out = xu_a;
    float* xi_out = xi_a;

    const int scatter_blocks = ((EE / 4) * 32 + 255) / 256;

    for (int l = 0; l < LL; ++l) {
        zero_kernel<<<2048, 256>>>((float4*)aggi, NI * C / 4);
        zero_kernel<<<2048, 256>>>((float4*)aggu, NU * C / 4);
        scatter_kernel<<<scatter_blocks, 256>>>(xu_in, e_ui_src, e_ui_dst, aggi, EE);
        scatter_kernel<<<scatter_blocks, 256>>>(xi_in, e_iu_src, e_iu_dst, aggu, EE);
        // items: weights (l,0); LN params (l,1)
        gemm_tc<<<(NI + 255) / 256, 512, GEMM_SMEM_BYTES>>>(
            aggi, xi_in, wfrag + (size_t)(l * 2 + 0) * 16 * 16 * 32,
            bias + (l * 2 + 0) * C, ln_g + (l * 2 + 1) * C, ln_b + (l * 2 + 1) * C,
            xi_out, NI);
        // users: weights (l,1); LN params (l,0)
        gemm_tc<<<(NU + 255) / 256, 512, GEMM_SMEM_BYTES>>>(
            aggu, xu_in, wfrag + (size_t)(l * 2 + 1) * 16 * 16 * 32,
            bias + (l * 2 + 1) * C, ln_g + (l * 2 + 0) * C, ln_b + (l * 2 + 0) * C,
            xu_out, NU);
        xu_in = xu_out; xi_in = xi_out;
        xu_out = xu_b;  xi_out = xi_b;
    }
    head_kernel<<<(BB * 32 + 255) / 256, 256>>>(xu_in, lin_w, lin_b, out);
}